// round 2
// baseline (speedup 1.0000x reference)
#include <cuda_runtime.h>

#define B   8
#define NC  2
#define NS  8
#define CH  64
#define H   192
#define WI  192
#define HW  (H*WI)

// ---------------- scratch (static __device__, no allocs) ----------------
__device__ float d_prob[B*NC*HW];        // sigmoid(class_score)     [(b*2+c)*HW + hw]
__device__ float d_g[B*NC*HW];           // g(p) map                 [(b*2+c)*HW + hw]
__device__ float d_sp[B*NC*NS*HW];       // raw space maps           [((b*2+c)*8+s)*HW + hw]
__device__ float d_Z[B*NC*NS];           // per-map sums
__device__ float d_inv[B*NC*NS];         // Wcs[s]/Z
__device__ float d_S[B*NC*NS*576];       // shifted correlations     [chn*576 + i*9 + ky*3+kx]
__device__ float d_tok2[B*NC*CH];        // [(b*2+c)*64 + d]
__device__ float d_M[B*CH*24];           // [(b*64+o)*24 + c*12 + k]   (k = ky*3+kx)
__device__ float d_sum[CH];
__device__ float d_ss[CH];
__device__ float d_scale[CH];
__device__ float d_shift[CH];

__device__ __forceinline__ float sigm(float x) { return 1.f/(1.f + __expf(-x)); }

// ---------------- K0: zero accumulators ----------------
__global__ void k_zero() {
    int i = blockIdx.x*256 + threadIdx.x;
    if (i < B*NC*NS*576) d_S[i] = 0.f;
    if (i < B*NC*NS)     d_Z[i] = 0.f;
    if (i < B*NC*CH)     d_tok2[i] = 0.f;
    if (i < CH) { d_sum[i] = 0.f; d_ss[i] = 0.f; }
}

// ---------------- K1: prob = sigmoid(score), g = sum_s Wc*Wcv*sigmoid(Wa*p) ----------------
__global__ void k_prob_g(const float* __restrict__ score,
                         const float* __restrict__ Wcv,
                         const float* __restrict__ Wa,
                         const float* __restrict__ Wc) {
    int i = blockIdx.x*256 + threadIdx.x;          // exact: 2304*256 = 589824
    float p = sigm(score[i]);
    d_prob[i] = p;
    float g = 0.f;
#pragma unroll
    for (int s = 0; s < NS; s++)
        g += (Wc[s]*Wcv[s]) * sigm(Wa[s]*p);
    d_g[i] = g;
}

// ---------------- K2: space maps (ch0 = prob, ch1..7 = sigmoid(conv3x3(prob))) + per-map sums ----------------
__global__ void k_space(const float* __restrict__ Wk) {
    __shared__ float wk[63];
    int tid = threadIdx.x;
    if (tid < 63) wk[tid] = Wk[tid];
    __syncthreads();
    int bc = blockIdx.y;
    int p  = blockIdx.x*256 + tid;                 // exact: 144*256 = 36864
    int h = p / WI, w = p % WI;
    const float* pr = d_prob + bc*HW;
    float win[9];
#pragma unroll
    for (int u = 0; u < 3; u++)
#pragma unroll
        for (int v = 0; v < 3; v++) {
            int hh = h + u - 1, ww = w + v - 1;
            win[u*3+v] = (hh >= 0 && hh < H && ww >= 0 && ww < WI) ? pr[hh*WI + ww] : 0.f;
        }
    float val[8];
    val[0] = win[4];
#pragma unroll
    for (int k = 0; k < 7; k++) {
        float a = 0.f;
#pragma unroll
        for (int j = 0; j < 9; j++) a += wk[k*9+j]*win[j];
        val[k+1] = sigm(a);
    }
#pragma unroll
    for (int k = 0; k < 8; k++) d_sp[(bc*8+k)*HW + p] = val[k];
#pragma unroll
    for (int k = 0; k < 8; k++) {
        float v = val[k];
#pragma unroll
        for (int o = 16; o > 0; o >>= 1) v += __shfl_xor_sync(0xffffffffu, v, o);
        if ((tid & 31) == 0) atomicAdd(&d_Z[bc*8+k], v);
    }
}

// ---------------- K3: inv = W_combine_space[s] / Z  (fold 1x1 combine into normalization) ----------------
__global__ void k_inv(const float* __restrict__ Wcs) {
    int i = threadIdx.x;                           // 128
    d_inv[i] = Wcs[i & 7] / d_Z[i];
}

// ---------------- K4: S[b,c,s,i,ky,kx] = sum_hw x[b,i,hw] * sn[b,c,s, h+1-ky, w+1-kx] ----------------
// block: 128 threads = 8 channel-groups x 16 maps; thread accumulates 8ch x 9tap outer product.
// grid: (rowband=48 x 4 rows, coltile=3 x 64 cols, b=8)
__global__ __launch_bounds__(128) void k_S(const float* __restrict__ x) {
    __shared__ float sn_s[16*397];                 // 16 maps x (6 rows x 66 cols), pitch 397 (bank-spread)
    __shared__ float x_s[64*65];                   // 64 ch x 64 cols, pitch 65
    int rb = blockIdx.x, ct = blockIdx.y, b = blockIdx.z;
    int tid = threadIdx.x;
    int map = tid & 15, cg = tid >> 4;

    for (int idx = tid; idx < 16*6*66; idx += 128) {
        int m = idx/396, rem = idx%396, r = rem/66, cc = rem%66;
        int gr = rb*4 - 1 + r, gc = ct*64 - 1 + cc;
        int chn = (b*NC + (m >> 3))*NS + (m & 7);
        float v = 0.f;
        if (gr >= 0 && gr < H && gc >= 0 && gc < WI)
            v = d_sp[chn*HW + gr*WI + gc] * d_inv[chn];
        sn_s[m*397 + r*66 + cc] = v;
    }

    float acc[8][9];
#pragma unroll
    for (int ci = 0; ci < 8; ci++)
#pragma unroll
        for (int k = 0; k < 9; k++) acc[ci][k] = 0.f;

    for (int r = 0; r < 4; r++) {
        __syncthreads();
        int hh = rb*4 + r;
        for (int idx = tid; idx < 64*64; idx += 128) {
            int ch = idx >> 6, col = idx & 63;
            x_s[ch*65 + col] = x[((b*CH + ch)*H + hh)*WI + ct*64 + col];
        }
        __syncthreads();
        const float* snp = &sn_s[map*397 + r*66];
        const float* xp  = &x_s[cg*8*65];
        for (int j = 0; j < 64; j++) {
            float w0 = snp[j],       w1 = snp[j+1],       w2 = snp[j+2];
            float w3 = snp[66+j],    w4 = snp[66+j+1],    w5 = snp[66+j+2];
            float w6 = snp[132+j],   w7 = snp[132+j+1],   w8 = snp[132+j+2];
#pragma unroll
            for (int ci = 0; ci < 8; ci++) {
                float xv = xp[ci*65 + j];
                acc[ci][0] += xv*w0; acc[ci][1] += xv*w1; acc[ci][2] += xv*w2;
                acc[ci][3] += xv*w3; acc[ci][4] += xv*w4; acc[ci][5] += xv*w5;
                acc[ci][6] += xv*w6; acc[ci][7] += xv*w7; acc[ci][8] += xv*w8;
            }
        }
    }
    int chn = (b*NC + (map >> 3))*NS + (map & 7);
    float* Sb = &d_S[chn*576];
#pragma unroll
    for (int ci = 0; ci < 8; ci++) {
        int i = cg*8 + ci;
#pragma unroll
        for (int ky = 0; ky < 3; ky++)
#pragma unroll
            for (int kx = 0; kx < 3; kx++)
                atomicAdd(&Sb[i*9 + ky*3 + kx], acc[ci][(2-ky)*3 + (2-kx)]);
    }
}

// ---------------- K5: tok2[b,c,d] = sum_{s,i,tau} Wx[(s*64+d),i,tau] * S'[b,c,s,i,tau] ----------------
__global__ void k_tok(const float* __restrict__ Wx) {
    __shared__ float Ss[576];
    int bcs = blockIdx.x;                          // ((b*2+c)*8+s), 128 blocks
    int tid = threadIdx.x;                         // 64 = d
    for (int i = tid; i < 576; i += 64) Ss[i] = d_S[bcs*576 + i];
    __syncthreads();
    int s = bcs & 7;
    const float4* wr = (const float4*)(Wx + (s*64 + tid)*576);
    const float4* sr = (const float4*)Ss;
    float a0 = 0.f, a1 = 0.f, a2 = 0.f, a3 = 0.f;
#pragma unroll 4
    for (int j = 0; j < 144; j++) {
        float4 wv = wr[j]; float4 sv = sr[j];
        a0 += wv.x*sv.x; a1 += wv.y*sv.y; a2 += wv.z*sv.z; a3 += wv.w*sv.w;
    }
    atomicAdd(&d_tok2[(bcs >> 3)*64 + tid], (a0 + a1) + (a2 + a3));
}

// ---------------- K6: M[b,c,o,tau] = sum_i W_single[o,i,tau] * tok2[b,c,i] ----------------
__global__ void k_M(const float* __restrict__ Ws) {
    __shared__ float t2[128];
    int b = blockIdx.x, tid = threadIdx.x;         // 128
    t2[tid] = d_tok2[b*128 + tid];
    __syncthreads();
    for (int idx = tid; idx < 1152; idx += 128) {
        int o = idx/18, rem = idx%18, c = rem/9, k = rem%9;
        const float* wp = Ws + o*576 + k;
        const float* tp = t2 + c*64;
        float a = 0.f;
#pragma unroll 8
        for (int i = 0; i < 64; i++) a += wp[i*9]*tp[i];
        d_M[(b*64 + o)*24 + c*12 + k] = a;
    }
}

// ---------------- K7: per-channel sum / sumsq of y0 (recomputed from g and M) ----------------
__global__ __launch_bounds__(256) void k_stats() {
    __shared__ float g_s[2*10*200];
    __shared__ float M_s[64*24];
    __shared__ float red1[256], red2[256];
    int band = blockIdx.x, b = blockIdx.y;
    int tid = threadIdx.x;
    for (int idx = tid; idx < 2*10*194; idx += 256) {
        int c = idx/1940, rem = idx%1940, r = rem/194, cc = rem%194;
        int gr = band*8 - 1 + r, gc = cc - 1;
        float v = 0.f;
        if (gr >= 0 && gr < H && gc >= 0 && gc < WI) v = d_g[(b*2 + c)*HW + gr*WI + gc];
        g_s[c*2000 + r*200 + cc] = v;
    }
    for (int idx = tid; idx < 64*24; idx += 256) M_s[idx] = d_M[b*64*24 + idx];
    __syncthreads();

    int o = tid & 63, cg = tid >> 6;
    float m[18];
#pragma unroll
    for (int k = 0; k < 9; k++) { m[k] = M_s[o*24 + k]; m[9+k] = M_s[o*24 + 12 + k]; }
    float sum = 0.f, ssq = 0.f;
    for (int r = 0; r < 8; r++) {
        for (int jt = 0; jt < 12; jt++) {
            int j = cg*48 + jt*4;
            float wv[2][3][6];
#pragma unroll
            for (int c = 0; c < 2; c++)
#pragma unroll
                for (int u = 0; u < 3; u++) {
                    const float* gp = &g_s[c*2000 + (r+u)*200 + j];
                    float4 A  = *(const float4*)gp;
                    float4 Bv = *(const float4*)(gp + 4);
                    wv[c][u][0]=A.x;  wv[c][u][1]=A.y;  wv[c][u][2]=A.z;
                    wv[c][u][3]=A.w;  wv[c][u][4]=Bv.x; wv[c][u][5]=Bv.y;
                }
#pragma unroll
            for (int q = 0; q < 4; q++) {
                float y0 = 0.f;
#pragma unroll
                for (int c = 0; c < 2; c++)
#pragma unroll
                    for (int ky = 0; ky < 3; ky++)
#pragma unroll
                        for (int kx = 0; kx < 3; kx++)
                            y0 += m[c*9 + ky*3 + kx]*wv[c][ky][q+kx];
                sum += y0; ssq += y0*y0;
            }
        }
    }
    red1[tid] = sum; red2[tid] = ssq;
    __syncthreads();
    if (tid < 64) {
        float s1 = red1[tid] + red1[64+tid] + red1[128+tid] + red1[192+tid];
        float s2 = red2[tid] + red2[64+tid] + red2[128+tid] + red2[192+tid];
        atomicAdd(&d_sum[tid], s1);
        atomicAdd(&d_ss[tid],  s2);
    }
}

// ---------------- K7b: finalize BN scale/shift ----------------
__global__ void k_bn(const float* __restrict__ gamma, const float* __restrict__ beta) {
    int o = threadIdx.x;                           // 64
    float n = (float)(B*HW);
    float mean = d_sum[o]/n;
    float var  = d_ss[o]/n - mean*mean;
    float sc = gamma[o]*rsqrtf(var + 1e-5f);
    d_scale[o] = sc;
    d_shift[o] = beta[o] - mean*sc;
}

// ---------------- K8: out = x + relu(y0*scale + shift), y0 recomputed ----------------
__global__ __launch_bounds__(256) void k_out(const float* __restrict__ x, float* __restrict__ out) {
    __shared__ float g_s[2*10*200];
    __shared__ float M_s[64*24];
    __shared__ float sc_s[64], sh_s[64];
    int band = blockIdx.x, b = blockIdx.y;
    int tid = threadIdx.x;
    for (int idx = tid; idx < 2*10*194; idx += 256) {
        int c = idx/1940, rem = idx%1940, r = rem/194, cc = rem%194;
        int gr = band*8 - 1 + r, gc = cc - 1;
        float v = 0.f;
        if (gr >= 0 && gr < H && gc >= 0 && gc < WI) v = d_g[(b*2 + c)*HW + gr*WI + gc];
        g_s[c*2000 + r*200 + cc] = v;
    }
    for (int idx = tid; idx < 64*24; idx += 256) M_s[idx] = d_M[b*64*24 + idx];
    if (tid < 64) { sc_s[tid] = d_scale[tid]; sh_s[tid] = d_shift[tid]; }
    __syncthreads();

    for (int p = tid; p < 8*192; p += 256) {
        int r = p/192, w = p%192;
        int hh = band*8 + r;
        float win[18];
#pragma unroll
        for (int c = 0; c < 2; c++)
#pragma unroll
            for (int ky = 0; ky < 3; ky++)
#pragma unroll
                for (int kx = 0; kx < 3; kx++)
                    win[c*9 + ky*3 + kx] = g_s[c*2000 + (r+ky)*200 + (w+kx)];
        int base = (b*CH)*HW + hh*WI + w;
#pragma unroll 4
        for (int o = 0; o < 64; o++) {
            const float* Mo = &M_s[o*24];
            float y0 = 0.f;
#pragma unroll
            for (int k = 0; k < 9; k++) y0 += Mo[k]*win[k];
#pragma unroll
            for (int k = 0; k < 9; k++) y0 += Mo[12+k]*win[9+k];
            float v = fmaxf(y0*sc_s[o] + sh_s[o], 0.f);
            int gi = base + o*HW;
            out[gi] = x[gi] + v;
        }
    }
}

// ---------------- launch ----------------
extern "C" void kernel_launch(void* const* d_in, const int* in_sizes, int n_in,
                              void* d_out, int out_size) {
    const float* x     = (const float*)d_in[0];
    const float* score = (const float*)d_in[1];
    const float* Wk    = (const float*)d_in[2];   // W_cspace (7,1,3,3)
    const float* Wx    = (const float*)d_in[3];   // W_xspace (512,64,3,3)
    const float* Wcs   = (const float*)d_in[4];   // W_combine_space (8)
    const float* Wcv   = (const float*)d_in[5];   // W_cvalue (8)
    const float* Wa    = (const float*)d_in[6];   // W_attn (8)
    const float* Wc    = (const float*)d_in[7];   // W_combine (8)
    const float* Ws    = (const float*)d_in[8];   // W_single (64,64,3,3)
    const float* gamma = (const float*)d_in[9];
    const float* beta  = (const float*)d_in[10];
    float* out = (float*)d_out;

    k_zero<<<288, 256>>>();
    k_prob_g<<<2304, 256>>>(score, Wcv, Wa, Wc);
    { dim3 g(144, 16); k_space<<<g, 256>>>(Wk); }
    k_inv<<<1, 128>>>(Wcs);
    { dim3 g(48, 3, 8); k_S<<<g, 128>>>(x); }
    k_tok<<<128, 64>>>(Wx);
    k_M<<<8, 128>>>(Ws);
    { dim3 g(24, 8); k_stats<<<g, 256>>>(); }
    k_bn<<<1, 64>>>(gamma, beta);
    { dim3 g(24, 8); k_out<<<g, 256>>>(x, out); }
}